// round 4
// baseline (speedup 1.0000x reference)
#include <cuda_runtime.h>

#define NN 256
#define SS 64
#define BB 1024
#define UNFOLDS 12
#define TB 8

// Scratch (device globals — no allocations allowed)
__device__ float4 g_params[(NN + 8) * NN];   // [i][j] {a, b, hwe, hw}, padded rows for branchless prefetch
__device__ float4 g_sparams[SS * NN];        // sensory {a, b, we, wsp}
__device__ float  g_sum_hw[NN];
__device__ float  g_sum_hwe[NN];
__device__ float  g_cmt[NN];
__device__ float  g_gl[NN];
__device__ float  g_gv[NN];
__device__ float  g_ncon[BB * NN];           // per-(b,j) step-invariant numerator constant
__device__ float  g_dcon[BB * NN];           // per-(b,j) step-invariant denominator constant

__device__ __forceinline__ float tanh_fast(float x) {
    float t;
    asm("tanh.approx.f32 %0, %1;" : "=f"(t) : "f"(x));
    return t;
}

__device__ __forceinline__ float softplus_f(float x) {
    return log1pf(expf(x));   // inputs are in small safe ranges
}

// ---------------------------------------------------------------------------
// Pack recurrent params: sigmoid(s*(v-m)) = 0.5*(1 + tanh(0.5*s*v - 0.5*s*m))
// contribution = wsp*sig = hw + hw*t, with hw = 0.5*softplus(w)*mask
// ---------------------------------------------------------------------------
__global__ void k_prep(const float* __restrict__ w, const float* __restrict__ sigma,
                       const float* __restrict__ mu, const float* __restrict__ erev,
                       const float* __restrict__ mask) {
    int i = blockIdx.x, j = threadIdx.x;
    int idx = i * NN + j;
    float hw = 0.5f * softplus_f(w[idx]) * mask[idx];
    float a  = 0.5f * sigma[idx];
    float4 p;
    p.x = a;
    p.y = -a * mu[idx];
    p.z = hw * erev[idx];
    p.w = hw;
    g_params[idx] = p;
}

__global__ void k_sprep(const float* __restrict__ sw, const float* __restrict__ ssig,
                        const float* __restrict__ smu, const float* __restrict__ serev,
                        const float* __restrict__ smask) {
    int s = blockIdx.x, j = threadIdx.x;
    int idx = s * NN + j;
    float wsp = softplus_f(sw[idx]) * smask[idx];
    float a   = 0.5f * ssig[idx];
    float4 p;
    p.x = a;
    p.y = -a * smu[idx];
    p.z = wsp * serev[idx];
    p.w = wsp;
    g_sparams[idx] = p;
}

// Column sums of hw/hwe + per-neuron scalars
__global__ void k_colsums(const float* __restrict__ gleak, const float* __restrict__ vleak,
                          const float* __restrict__ cm) {
    int j = threadIdx.x;
    float shw = 0.f, shwe = 0.f;
    #pragma unroll 8
    for (int i = 0; i < NN; i++) {
        float4 p = g_params[i * NN + j];
        shw  += p.w;
        shwe += p.z;
    }
    g_sum_hw[j]  = shw;
    g_sum_hwe[j] = shwe;
    float gl = softplus_f(gleak[j]);
    g_gl[j]  = gl;
    g_gv[j]  = gl * vleak[j];
    g_cmt[j] = softplus_f(cm[j]) * (float)UNFOLDS;   // softplus(cm) / (1/12)
}

// Sensory pass + fold all step-invariant terms into per-(b,j) constants
__global__ void k_sens(const float* __restrict__ inputs) {
    __shared__ float xin[SS];
    int b = blockIdx.x, j = threadIdx.x;
    if (j < SS) xin[j] = inputs[b * SS + j];
    __syncthreads();
    float num = 0.f, den = 0.f;
    #pragma unroll 4
    for (int s = 0; s < SS; s++) {
        float4 p = g_sparams[s * NN + j];
        float t  = tanh_fast(fmaf(p.x, xin[s], p.y));
        float sg = fmaf(0.5f, t, 0.5f);
        num = fmaf(p.z, sg, num);
        den = fmaf(p.w, sg, den);
    }
    g_ncon[b * NN + j] = g_gv[j] + g_sum_hwe[j] + num;
    g_dcon[b * NN + j] = g_cmt[j] + g_gl[j] + g_sum_hw[j] + den + 1e-8f;
}

// ---------------------------------------------------------------------------
// Main: each CTA owns TB=8 batch rows, keeps v in SMEM through all 12 unfolds.
// Thread j owns output neuron j; inner loop streams the float4 param table
// from L2 with a 4-row register prefetch.
// ---------------------------------------------------------------------------
__global__ void __launch_bounds__(256) k_main(const float* __restrict__ state,
                                              float* __restrict__ out) {
    __shared__ float v_sh[TB][NN];
    __shared__ float nc[TB][NN];
    __shared__ float dc[TB][NN];

    int j  = threadIdx.x;
    int b0 = blockIdx.x * TB;

    #pragma unroll
    for (int b = 0; b < TB; b++) {
        int g = (b0 + b) * NN + j;
        v_sh[b][j] = state[g];
        nc[b][j]   = g_ncon[g];
        dc[b][j]   = g_dcon[g];
    }
    float cmt = g_cmt[j];
    __syncthreads();

    const float4* P = g_params + j;   // stride NN between i-rows

    for (int step = 0; step < UNFOLDS; step++) {
        float num[TB], den[TB];
        #pragma unroll
        for (int b = 0; b < TB; b++) { num[b] = 0.f; den[b] = 0.f; }

        float4 p0 = P[0], p1 = P[NN], p2 = P[2 * NN], p3 = P[3 * NN];

        for (int i = 0; i < NN; i += 4) {
            float4 c0 = p0, c1 = p1, c2 = p2, c3 = p3;
            // branchless prefetch into padded rows beyond i=255
            p0 = P[(i + 4) * NN];
            p1 = P[(i + 5) * NN];
            p2 = P[(i + 6) * NN];
            p3 = P[(i + 7) * NN];

            #pragma unroll
            for (int b = 0; b < TB; b++) {
                float4 v = *reinterpret_cast<const float4*>(&v_sh[b][i]);  // broadcast LDS.128
                float t0 = tanh_fast(fmaf(c0.x, v.x, c0.y));
                float t1 = tanh_fast(fmaf(c1.x, v.y, c1.y));
                float t2 = tanh_fast(fmaf(c2.x, v.z, c2.y));
                float t3 = tanh_fast(fmaf(c3.x, v.w, c3.y));
                num[b] = fmaf(c0.z, t0, num[b]); den[b] = fmaf(c0.w, t0, den[b]);
                num[b] = fmaf(c1.z, t1, num[b]); den[b] = fmaf(c1.w, t1, den[b]);
                num[b] = fmaf(c2.z, t2, num[b]); den[b] = fmaf(c2.w, t2, den[b]);
                num[b] = fmaf(c3.z, t3, num[b]); den[b] = fmaf(c3.w, t3, den[b]);
            }
        }

        float vn[TB];
        #pragma unroll
        for (int b = 0; b < TB; b++)
            vn[b] = (fmaf(cmt, v_sh[b][j], nc[b][j]) + num[b]) / (den[b] + dc[b][j]);

        __syncthreads();                     // all reads of v_sh done
        #pragma unroll
        for (int b = 0; b < TB; b++) v_sh[b][j] = vn[b];
        __syncthreads();
    }

    #pragma unroll
    for (int b = 0; b < TB; b++)
        out[(b0 + b) * NN + j] = v_sh[b][j];
}

extern "C" void kernel_launch(void* const* d_in, const int* in_sizes, int n_in,
                              void* d_out, int out_size) {
    const float* inputs = (const float*)d_in[0];
    const float* state  = (const float*)d_in[1];
    const float* gleak  = (const float*)d_in[2];
    const float* vleak  = (const float*)d_in[3];
    const float* cm     = (const float*)d_in[4];
    const float* w      = (const float*)d_in[5];
    const float* sigma  = (const float*)d_in[6];
    const float* mu     = (const float*)d_in[7];
    const float* erev   = (const float*)d_in[8];
    const float* sw     = (const float*)d_in[9];
    const float* ssig   = (const float*)d_in[10];
    const float* smu    = (const float*)d_in[11];
    const float* serev  = (const float*)d_in[12];
    const float* mask   = (const float*)d_in[13];
    const float* smask  = (const float*)d_in[14];
    float* out = (float*)d_out;

    k_prep   <<<NN, NN>>>(w, sigma, mu, erev, mask);
    k_sprep  <<<SS, NN>>>(sw, ssig, smu, serev, smask);
    k_colsums<<<1,  NN>>>(gleak, vleak, cm);
    k_sens   <<<BB, NN>>>(inputs);
    k_main   <<<BB / TB, NN>>>(state, out);
}

// round 5
// speedup vs baseline: 1.1447x; 1.1447x over previous
#include <cuda_runtime.h>
#include <cuda_fp16.h>

#define NN 256
#define SS 64
#define BB 1024
#define UNFOLDS 12
#define TB 8
#define NPAIR (NN / 2)   // 128 i-pairs
#define NBLK  (NN / 8)   // 32 blocks of 8 i's (4 pairs)

// Scratch (device globals — no allocations allowed)
__device__ uint2  g_ab[NPAIR * NN];      // per (pair,j): {a2, b2} as f16x2 (lo=even i, hi=odd i)
__device__ float4 g_we[NPAIR * NN];      // per (pair,j): {hwe_lo, hwe_hi, hw_lo, hw_hi} fp32
__device__ float4 g_sparams[SS * NN];    // sensory {a, b, we, wsp} fp32
__device__ float  g_sum_hw[NN];
__device__ float  g_sum_hwe[NN];
__device__ float  g_cmt[NN];
__device__ float  g_gl[NN];
__device__ float  g_gv[NN];
__device__ float  g_ncon[BB * NN];       // per-(b,j) step-invariant numerator constant
__device__ float  g_dcon[BB * NN];       // per-(b,j) step-invariant denominator constant

__device__ __forceinline__ float tanh_fast(float x) {
    float t;
    asm("tanh.approx.f32 %0, %1;" : "=f"(t) : "f"(x));
    return t;
}

__device__ __forceinline__ float softplus_f(float x) {
    return log1pf(expf(x));   // inputs are in small safe ranges
}

// Process one i-pair for one batch row:
//   arg2 = a2 * v2 + b2            (f16x2 HFMA2)
//   t2   = tanh(arg2)              (f16x2 MUFU — 2 tanh in 1 op)
//   num2 += we2 * t2f              (f32x2 FFMA2 — 2 fp32 FMA in 1 op)
//   den2 += wh2 * t2f
__device__ __forceinline__ void proc_pair(unsigned v2, uint2 ab,
                                          unsigned long long we2, unsigned long long wh2,
                                          unsigned long long& num2, unsigned long long& den2) {
    unsigned arg, t;
    asm("fma.rn.f16x2 %0, %1, %2, %3;" : "=r"(arg) : "r"(ab.x), "r"(v2), "r"(ab.y));
    asm("tanh.approx.f16x2 %0, %1;" : "=r"(t) : "r"(arg));
    float tlo, thi;
    asm("{ .reg .b16 l, h;\n\t"
        "  mov.b32 {l, h}, %2;\n\t"
        "  cvt.f32.f16 %0, l;\n\t"
        "  cvt.f32.f16 %1, h; }"
        : "=f"(tlo), "=f"(thi) : "r"(t));
    unsigned long long T;
    asm("mov.b64 %0, {%1, %2};" : "=l"(T) : "f"(tlo), "f"(thi));
    asm("fma.rn.f32x2 %0, %1, %2, %3;" : "=l"(num2) : "l"(we2), "l"(T), "l"(num2));
    asm("fma.rn.f32x2 %0, %1, %2, %3;" : "=l"(den2) : "l"(wh2), "l"(T), "l"(den2));
}

// ---------------------------------------------------------------------------
// Pack recurrent params per i-pair:
// sigmoid(s*(v-m)) = 0.5*(1 + tanh(0.5*s*v - 0.5*s*m)); hw = 0.5*softplus(w)*mask
// ---------------------------------------------------------------------------
__global__ void k_prep(const float* __restrict__ w, const float* __restrict__ sigma,
                       const float* __restrict__ mu, const float* __restrict__ erev,
                       const float* __restrict__ mask) {
    int p = blockIdx.x, j = threadIdx.x;
    int x0 = (2 * p) * NN + j;
    int x1 = (2 * p + 1) * NN + j;

    float a0 = 0.5f * sigma[x0], a1 = 0.5f * sigma[x1];
    float hw0 = 0.5f * softplus_f(w[x0]) * mask[x0];
    float hw1 = 0.5f * softplus_f(w[x1]) * mask[x1];

    __half2 A = __floats2half2_rn(a0, a1);
    __half2 Bv = __floats2half2_rn(-a0 * mu[x0], -a1 * mu[x1]);
    uint2 ab;
    ab.x = *reinterpret_cast<unsigned*>(&A);
    ab.y = *reinterpret_cast<unsigned*>(&Bv);
    g_ab[p * NN + j] = ab;
    g_we[p * NN + j] = make_float4(hw0 * erev[x0], hw1 * erev[x1], hw0, hw1);
}

__global__ void k_sprep(const float* __restrict__ sw, const float* __restrict__ ssig,
                        const float* __restrict__ smu, const float* __restrict__ serev,
                        const float* __restrict__ smask) {
    int s = blockIdx.x, j = threadIdx.x;
    int idx = s * NN + j;
    float wsp = softplus_f(sw[idx]) * smask[idx];
    float a   = 0.5f * ssig[idx];
    float4 q;
    q.x = a;
    q.y = -a * smu[idx];
    q.z = wsp * serev[idx];
    q.w = wsp;
    g_sparams[idx] = q;
}

// Column sums of hw/hwe + per-neuron scalars
__global__ void k_colsums(const float* __restrict__ gleak, const float* __restrict__ vleak,
                          const float* __restrict__ cm) {
    int j = threadIdx.x;
    float shw = 0.f, shwe = 0.f;
    #pragma unroll 8
    for (int p = 0; p < NPAIR; p++) {
        float4 q = g_we[p * NN + j];
        shwe += q.x + q.y;
        shw  += q.z + q.w;
    }
    g_sum_hw[j]  = shw;
    g_sum_hwe[j] = shwe;
    float gl = softplus_f(gleak[j]);
    g_gl[j]  = gl;
    g_gv[j]  = gl * vleak[j];
    g_cmt[j] = softplus_f(cm[j]) * (float)UNFOLDS;   // softplus(cm) / (1/12)
}

// Sensory pass (fp32, step-invariant) + fold all constants into per-(b,j) terms
__global__ void k_sens(const float* __restrict__ inputs) {
    __shared__ float xin[SS];
    int b = blockIdx.x, j = threadIdx.x;
    if (j < SS) xin[j] = inputs[b * SS + j];
    __syncthreads();
    float num = 0.f, den = 0.f;
    #pragma unroll 4
    for (int s = 0; s < SS; s++) {
        float4 q = g_sparams[s * NN + j];
        float t  = tanh_fast(fmaf(q.x, xin[s], q.y));
        float sg = fmaf(0.5f, t, 0.5f);
        num = fmaf(q.z, sg, num);
        den = fmaf(q.w, sg, den);
    }
    g_ncon[b * NN + j] = g_gv[j] + g_sum_hwe[j] + num;
    g_dcon[b * NN + j] = g_cmt[j] + g_gl[j] + g_sum_hw[j] + den + 1e-8f;
}

// ---------------------------------------------------------------------------
// Main: each CTA owns TB=8 batch rows through all 12 unfolds.
// v lives in registers (fp32) + a half copy in SMEM for the HFMA2 args.
// Inner loop: 8 i's per block iteration, software-pipelined param loads.
// ---------------------------------------------------------------------------
__global__ void __launch_bounds__(256) k_main(const float* __restrict__ state,
                                              float* __restrict__ out) {
    __shared__ __half v_h[TB][NN];   // half copy of v for f16x2 args

    int j  = threadIdx.x;
    int b0 = blockIdx.x * TB;

    float vreg[TB], ncr[TB], dcr[TB];
    #pragma unroll
    for (int b = 0; b < TB; b++) {
        int g = (b0 + b) * NN + j;
        vreg[b] = state[g];
        ncr[b]  = g_ncon[g];
        dcr[b]  = g_dcon[g];
        v_h[b][j] = __float2half_rn(vreg[b]);
    }
    float cmt = g_cmt[j];
    __syncthreads();

    const uint2* AB = g_ab + j;                                        // stride NN per pair
    const ulonglong2* WE = reinterpret_cast<const ulonglong2*>(g_we) + j;  // {we2, wh2}

    for (int step = 0; step < UNFOLDS; step++) {
        unsigned long long num2[TB], den2[TB];   // f32x2 {even-i sum, odd-i sum}
        #pragma unroll
        for (int b = 0; b < TB; b++) { num2[b] = 0ull; den2[b] = 0ull; }

        // prefetch block 0 (4 pairs)
        uint2 ab[4];
        ulonglong2 we[4];
        #pragma unroll
        for (int p = 0; p < 4; p++) { ab[p] = AB[p * NN]; we[p] = WE[p * NN]; }

        for (int blk = 0; blk < NBLK; blk++) {
            uint2 cab[4];
            ulonglong2 cwe[4];
            #pragma unroll
            for (int p = 0; p < 4; p++) { cab[p] = ab[p]; cwe[p] = we[p]; }

            int nb = (blk + 1 < NBLK) ? blk + 1 : blk;   // clamp last prefetch
            #pragma unroll
            for (int p = 0; p < 4; p++) {
                ab[p] = AB[(nb * 4 + p) * NN];
                we[p] = WE[(nb * 4 + p) * NN];
            }

            #pragma unroll
            for (int b = 0; b < TB; b++) {
                // 8 halves = 4 half2 pairs, one broadcast LDS.128
                uint4 vh = *reinterpret_cast<const uint4*>(&v_h[b][blk * 8]);
                proc_pair(vh.x, cab[0], cwe[0].x, cwe[0].y, num2[b], den2[b]);
                proc_pair(vh.y, cab[1], cwe[1].x, cwe[1].y, num2[b], den2[b]);
                proc_pair(vh.z, cab[2], cwe[2].x, cwe[2].y, num2[b], den2[b]);
                proc_pair(vh.w, cab[3], cwe[3].x, cwe[3].y, num2[b], den2[b]);
            }
        }

        float vn[TB];
        #pragma unroll
        for (int b = 0; b < TB; b++) {
            float nlo, nhi, dlo, dhi;
            asm("mov.b64 {%0, %1}, %2;" : "=f"(nlo), "=f"(nhi) : "l"(num2[b]));
            asm("mov.b64 {%0, %1}, %2;" : "=f"(dlo), "=f"(dhi) : "l"(den2[b]));
            float num = nlo + nhi;
            float den = dlo + dhi;
            vn[b] = (fmaf(cmt, vreg[b], ncr[b]) + num) / (den + dcr[b]);
        }

        __syncthreads();                     // all reads of v_h done
        #pragma unroll
        for (int b = 0; b < TB; b++) {
            vreg[b] = vn[b];
            v_h[b][j] = __float2half_rn(vn[b]);
        }
        __syncthreads();
    }

    #pragma unroll
    for (int b = 0; b < TB; b++)
        out[(b0 + b) * NN + j] = vreg[b];
}

extern "C" void kernel_launch(void* const* d_in, const int* in_sizes, int n_in,
                              void* d_out, int out_size) {
    const float* inputs = (const float*)d_in[0];
    const float* state  = (const float*)d_in[1];
    const float* gleak  = (const float*)d_in[2];
    const float* vleak  = (const float*)d_in[3];
    const float* cm     = (const float*)d_in[4];
    const float* w      = (const float*)d_in[5];
    const float* sigma  = (const float*)d_in[6];
    const float* mu     = (const float*)d_in[7];
    const float* erev   = (const float*)d_in[8];
    const float* sw     = (const float*)d_in[9];
    const float* ssig   = (const float*)d_in[10];
    const float* smu    = (const float*)d_in[11];
    const float* serev  = (const float*)d_in[12];
    const float* mask   = (const float*)d_in[13];
    const float* smask  = (const float*)d_in[14];
    float* out = (float*)d_out;

    k_prep   <<<NPAIR, NN>>>(w, sigma, mu, erev, mask);
    k_sprep  <<<SS, NN>>>(sw, ssig, smu, serev, smask);
    k_colsums<<<1,  NN>>>(gleak, vleak, cm);
    k_sens   <<<BB, NN>>>(inputs);
    k_main   <<<BB / TB, NN>>>(state, out);
}